// round 14
// baseline (speedup 1.0000x reference)
#include <cuda_runtime.h>
#include <cuda_fp16.h>
#include <cstdint>

// Problem shape (fixed by the dataset)
#define D_IN     256
#define D_OUT    512
#define MAX_M    50048            // 391 * 128
#define MAX_CHUNKS 100096

// GEMM tiling
#define TILE_M 128
#define TILE_N 128
#define BK     64                     // fp16 per K-chunk (128 bytes per row)
#define NCHUNKS (D_IN / BK)           // 4
#define OP_BYTES  (128 * 128)         // 16KB A tile per stage
#define NSTAGES 3
#define SMEM_TOTAL (NSTAGES * OP_BYTES)   // 48KB (A only; B goes via LDG)

// B fragment table: [n8=64][ks=16][lane=32][2 regs] uint32
#define NFRAG_U32 (64 * 16 * 32 * 2)      // 65536 u32 = 256KB

// ---------------------------------------------------------------------------
// Scratch (device globals — allocation-free rule)
// ---------------------------------------------------------------------------
__device__ __half g_feat16[(size_t)MAX_CHUNKS * D_IN];   // fp16 chunk table
__device__ __half g_a[(size_t)MAX_M * D_IN];             // cell means, fp16
__device__ uint32_t g_bfrag[NFRAG_U32];                  // W in mma B-fragment order
__device__ int g_starts[MAX_M + 2];

// ---------------------------------------------------------------------------
// PTX helpers (legacy tensor-core path — tcgen05 NOT available through the
// harness's compute_103 virtual target)
// ---------------------------------------------------------------------------
__device__ __forceinline__ uint32_t smem_u32(const void* p) {
    uint32_t a;
    asm("{ .reg .u64 t; cvta.to.shared.u64 t, %1; cvt.u32.u64 %0, t; }"
        : "=r"(a) : "l"(p));
    return a;
}

#define CP_ASYNC16(dst_u32, src_ptr) \
    asm volatile("cp.async.cg.shared.global [%0], [%1], 16;" \
                 :: "r"(dst_u32), "l"(src_ptr))
#define CP_COMMIT() asm volatile("cp.async.commit_group;" ::: "memory")
#define CP_WAIT(n)  asm volatile("cp.async.wait_group %0;" :: "n"(n) : "memory")

#define LDSM_X4(r0, r1, r2, r3, addr) \
    asm volatile("ldmatrix.sync.aligned.m8n8.x4.shared.b16 {%0,%1,%2,%3}, [%4];" \
                 : "=r"(r0), "=r"(r1), "=r"(r2), "=r"(r3) : "r"(addr))

#define MMA_F16B(d, a, b0, b1) \
    asm volatile( \
        "mma.sync.aligned.m16n8k16.row.col.f32.f16.f16.f32 " \
        "{%0,%1,%2,%3}, {%4,%5,%6,%7}, {%8,%9}, {%0,%1,%2,%3};" \
        : "+f"((d)[0]), "+f"((d)[1]), "+f"((d)[2]), "+f"((d)[3]) \
        : "r"((a)[0]), "r"((a)[1]), "r"((a)[2]), "r"((a)[3]), \
          "r"(b0), "r"(b1))

// SW128-style swizzle for 128B rows
__device__ __forceinline__ uint32_t sw_off(int row, int colbyte) {
    return (uint32_t)(row * 128 + (colbyte ^ ((row & 7) << 4)));
}

__device__ __forceinline__ uint32_t pack_h2(float x, float y) {
    __half2 h = __floats2half2_rn(x, y);
    return *reinterpret_cast<uint32_t*>(&h);
}

// ---------------------------------------------------------------------------
// Prep kernel: block-range dispatch.
//   [0, FB)            : chunk_features fp32 -> fp16 (16 floats / thread)
//   [FB, FB+256)       : W -> B-fragment-order fp16 table
//   [FB+256, ...)      : per-cell start offsets (scatter from boundaries)
// ---------------------------------------------------------------------------
__global__ void prep_kernel(const float* __restrict__ feats,
                            const float* __restrict__ W,
                            const int* __restrict__ seg,
                            int n_feat_elems, int FB,
                            int M, int num_cells) {
    int b = blockIdx.x;
    if (b < FB) {
        int base = (b * 256 + threadIdx.x) * 16;
        if (base + 16 <= n_feat_elems) {
            float4 v0 = __ldg(reinterpret_cast<const float4*>(feats + base));
            float4 v1 = __ldg(reinterpret_cast<const float4*>(feats + base + 4));
            float4 v2 = __ldg(reinterpret_cast<const float4*>(feats + base + 8));
            float4 v3 = __ldg(reinterpret_cast<const float4*>(feats + base + 12));
            uint4 p0, p1;
            p0.x = pack_h2(v0.x, v0.y); p0.y = pack_h2(v0.z, v0.w);
            p0.z = pack_h2(v1.x, v1.y); p0.w = pack_h2(v1.z, v1.w);
            p1.x = pack_h2(v2.x, v2.y); p1.y = pack_h2(v2.z, v2.w);
            p1.z = pack_h2(v3.x, v3.y); p1.w = pack_h2(v3.z, v3.w);
            *reinterpret_cast<uint4*>(g_feat16 + base)     = p0;
            *reinterpret_cast<uint4*>(g_feat16 + base + 8) = p1;
        }
    } else if (b < FB + 256) {
        // B-fragment layout: t = (((n8*16 + ks)*32 + lane)*2 + r)
        // lane map (m16n8k16 B): n = n8*8 + lane/4, k = ks*16 + (lane%4)*2 + r*8
        // value = {W[k][n], W[k+1][n]} packed as half2
        int t = (b - FB) * 256 + threadIdx.x;     // 0..65535
        int r    = t & 1;
        int lane = (t >> 1) & 31;
        int ks   = (t >> 6) & 15;
        int n8   = t >> 10;
        int n = n8 * 8 + (lane >> 2);
        int k = ks * 16 + ((lane & 3) << 1) + (r << 3);
        float w0 = __ldg(W + (size_t)k * D_OUT + n);
        float w1 = __ldg(W + (size_t)(k + 1) * D_OUT + n);
        g_bfrag[t] = pack_h2(w0, w1);
    } else {
        int i = (b - FB - 256) * 256 + threadIdx.x;
        if (i >= M) return;
        int cur = seg[i];
        int prev = (i == 0) ? -1 : seg[i - 1];
        for (int c = prev + 1; c <= cur; ++c) g_starts[c] = i;
        if (i == M - 1)
            for (int c = cur + 1; c <= num_cells; ++c) g_starts[c] = M;
    }
}

// ---------------------------------------------------------------------------
// seg_mean: warp-per-cell gather (fp16 rows) + fp32 mean -> fp16 A
// 4-way unrolled member loop (MLP=4 independent row loads in flight).
// ---------------------------------------------------------------------------
__device__ __forceinline__ void acc_row(float* acc, uint4 v) {
    float2 f0 = __half22float2(*reinterpret_cast<__half2*>(&v.x));
    float2 f1 = __half22float2(*reinterpret_cast<__half2*>(&v.y));
    float2 f2 = __half22float2(*reinterpret_cast<__half2*>(&v.z));
    float2 f3 = __half22float2(*reinterpret_cast<__half2*>(&v.w));
    acc[0] += f0.x; acc[1] += f0.y; acc[2] += f1.x; acc[3] += f1.y;
    acc[4] += f2.x; acc[5] += f2.y; acc[6] += f3.x; acc[7] += f3.y;
}

__global__ void seg_mean_kernel(const int* __restrict__ midx, int num_cells) {
    int warp = (blockIdx.x * blockDim.x + threadIdx.x) >> 5;
    int lane = threadIdx.x & 31;
    if (warp >= num_cells) return;

    int s = g_starts[warp];
    int e = g_starts[warp + 1];

    float acc[8];
    #pragma unroll
    for (int i = 0; i < 8; ++i) acc[i] = 0.f;

    int j = s;
    for (; j + 4 <= e; j += 4) {
        int i0 = __ldg(midx + j);
        int i1 = __ldg(midx + j + 1);
        int i2 = __ldg(midx + j + 2);
        int i3 = __ldg(midx + j + 3);
        uint4 v0 = __ldg(reinterpret_cast<const uint4*>(
                             g_feat16 + (size_t)i0 * D_IN) + lane);
        uint4 v1 = __ldg(reinterpret_cast<const uint4*>(
                             g_feat16 + (size_t)i1 * D_IN) + lane);
        uint4 v2 = __ldg(reinterpret_cast<const uint4*>(
                             g_feat16 + (size_t)i2 * D_IN) + lane);
        uint4 v3 = __ldg(reinterpret_cast<const uint4*>(
                             g_feat16 + (size_t)i3 * D_IN) + lane);
        acc_row(acc, v0);
        acc_row(acc, v1);
        acc_row(acc, v2);
        acc_row(acc, v3);
    }
    for (; j < e; ++j) {
        uint4 v = __ldg(reinterpret_cast<const uint4*>(
                            g_feat16 + (size_t)__ldg(midx + j) * D_IN) + lane);
        acc_row(acc, v);
    }

    int cnt = e - s;
    float inv = 1.0f / (float)(cnt > 0 ? cnt : 1);

    uint4 p;
    p.x = pack_h2(acc[0] * inv, acc[1] * inv);
    p.y = pack_h2(acc[2] * inv, acc[3] * inv);
    p.z = pack_h2(acc[4] * inv, acc[5] * inv);
    p.w = pack_h2(acc[6] * inv, acc[7] * inv);
    *reinterpret_cast<uint4*>(g_a + (size_t)warp * D_IN + 8 * lane) = p;
}

// ---------------------------------------------------------------------------
// GEMM: mma.sync fp16  out[M,512] = A[M,256] @ W[256,512] + bias
// A: 128x128 tile via 3-stage cp.async smem pipeline (LDSM).
// B: direct LDG.64 per-lane fragments from g_bfrag (no smem, no ldmatrix) —
//    removes the x4 smem reread amplification; warps sharing wn hit L1.
// 8 warps: warp (wm in 0..3, wn in 0..1) computes 32(M) x 64(N). 2 CTAs/SM.
// ---------------------------------------------------------------------------
__device__ __forceinline__ void load_stage_A(uint32_t stage_u32, int m_base,
                                             int kchunk) {
    int tid = threadIdx.x;
    const char* gA = reinterpret_cast<const char*>(g_a);
    int kbyte = kchunk * BK * 2;
    #pragma unroll
    for (int i = 0; i < 4; ++i) {
        int seg = tid + i * 256;           // 0..1023
        int r = seg >> 3;                  // 0..127
        int cb = (seg & 7) << 4;           // 0..112
        CP_ASYNC16(stage_u32 + sw_off(r, cb),
                   gA + (size_t)(m_base + r) * (D_IN * 2) + kbyte + cb);
    }
}

__global__ __launch_bounds__(256, 2)
void gemm_kernel(const float* __restrict__ bias, float* __restrict__ out, int M) {
    extern __shared__ char smem[];
    uint32_t sb = smem_u32(smem);

    int tid  = threadIdx.x;
    int wid  = tid >> 5;
    int lane = tid & 31;
    int wm = wid >> 1;           // 0..3  (M direction, 32 rows each)
    int wn = wid & 1;            // 0..1  (N direction, 64 cols each)

    int m_base = blockIdx.y * TILE_M;
    int n_base = blockIdx.x * TILE_N;

    // B fragment base (uint2 units): (n8g*16 + ksg)*32 + lane
    const uint2* bf = reinterpret_cast<const uint2*>(g_bfrag);
    int bbase = ((blockIdx.x * 16 + wn * 8) * 16) * 32 + lane;

    float acc[2][8][4];
    #pragma unroll
    for (int mt = 0; mt < 2; ++mt)
        #pragma unroll
        for (int nt = 0; nt < 8; ++nt)
            #pragma unroll
            for (int j = 0; j < 4; ++j)
                acc[mt][nt][j] = 0.f;

    // Prologue: fill first 2 of 3 A stages
    load_stage_A(sb, m_base, 0);
    CP_COMMIT();
    load_stage_A(sb + OP_BYTES, m_base, 1);
    CP_COMMIT();

    // ldmatrix lane offsets (A only)
    int a_row  = wm * 32 + (lane & 15);                     // + mt*16
    int a_cgrp = (lane >> 4) << 4;                          // 0 or 16

    #pragma unroll
    for (int c = 0; c < NCHUNKS; ++c) {
        CP_WAIT(1);          // A chunk c resident (this thread's copies)
        __syncthreads();     // cross-thread visibility of cp.async data

        if (c + 2 < NCHUNKS)
            load_stage_A(sb + (uint32_t)((c + 2) % NSTAGES) * OP_BYTES,
                         m_base, c + 2);
        CP_COMMIT();         // may be empty; keeps group accounting in lockstep

        uint32_t stage = sb + (uint32_t)(c % NSTAGES) * OP_BYTES;

        #pragma unroll
        for (int ks = 0; ks < 4; ++ks) {
            int ksg = c * 4 + ks;
            // B fragments: 8 independent LDG.64 (L1-hot after first touch)
            uint2 b[8];
            #pragma unroll
            for (int nt = 0; nt < 8; ++nt)
                b[nt] = __ldg(bf + bbase + nt * 512 + ksg * 32);

            int kb = ks * 32;
            uint32_t a[2][4];
            #pragma unroll
            for (int mt = 0; mt < 2; ++mt) {
                uint32_t off = sw_off(a_row + mt * 16, kb + a_cgrp);
                LDSM_X4(a[mt][0], a[mt][1], a[mt][2], a[mt][3], stage + off);
            }
            #pragma unroll
            for (int mt = 0; mt < 2; ++mt)
                #pragma unroll
                for (int nt = 0; nt < 8; ++nt)
                    MMA_F16B(acc[mt][nt], a[mt], b[nt].x, b[nt].y);
        }
    }

    // Epilogue: bias add + guarded stores
    int g = lane >> 2;           // row within m16 tile
    int q = lane & 3;            // col pair within n8 tile
    #pragma unroll
    for (int mt = 0; mt < 2; ++mt) {
        int r0 = m_base + wm * 32 + mt * 16 + g;
        #pragma unroll
        for (int nt = 0; nt < 8; ++nt) {
            int col = n_base + wn * 64 + nt * 8 + q * 2;
            float2 bv = *reinterpret_cast<const float2*>(bias + col);
            if (r0 < M) {
                float2 o = make_float2(acc[mt][nt][0] + bv.x,
                                       acc[mt][nt][1] + bv.y);
                *reinterpret_cast<float2*>(out + (size_t)r0 * D_OUT + col) = o;
            }
            if (r0 + 8 < M) {
                float2 o = make_float2(acc[mt][nt][2] + bv.x,
                                       acc[mt][nt][3] + bv.y);
                *reinterpret_cast<float2*>(out + (size_t)(r0 + 8) * D_OUT + col) = o;
            }
        }
    }
}

// ---------------------------------------------------------------------------
// Launch
// Inputs (metadata order): chunk_features, member_idx, segment_ids, num_cells, W, b
// ---------------------------------------------------------------------------
extern "C" void kernel_launch(void* const* d_in, const int* in_sizes, int n_in,
                              void* d_out, int out_size) {
    const float* feats = (const float*)d_in[0];
    const int*   midx  = (const int*)d_in[1];
    const int*   seg   = (const int*)d_in[2];
    const float* W     = (const float*)d_in[4];
    const float* bias  = (const float*)d_in[5];
    float* out = (float*)d_out;

    int n_feat    = in_sizes[0];          // 25.6M floats
    int M_members = in_sizes[1];          // 400000
    int num_cells = out_size / D_OUT;     // 50000

    // A: fused prep — feats fp16 convert | W fragment table | seg starts
    {
        int FB = (n_feat / 16 + 255) / 256;                 // feats blocks
        int SB = (M_members + 255) / 256;                   // starts blocks
        prep_kernel<<<FB + 256 + SB, 256>>>(feats, W, seg,
                                            n_feat, FB, M_members, num_cells);
    }

    // B: gather + segment mean (fp16 table) -> fp16 A
    {
        int total_threads = num_cells * 32;
        seg_mean_kernel<<<(total_threads + 255) / 256, 256>>>(midx, num_cells);
    }

    // C: tensor-core projection GEMM + bias (A smem-piped, B direct-LDG frags)
    {
        static bool attr_set = false;
        if (!attr_set) {
            cudaFuncSetAttribute(gemm_kernel,
                                 cudaFuncAttributeMaxDynamicSharedMemorySize,
                                 SMEM_TOTAL);
            attr_set = true;
        }
        dim3 grid(D_OUT / TILE_N, (num_cells + TILE_M - 1) / TILE_M);
        gemm_kernel<<<grid, 256, SMEM_TOTAL>>>(bias, out, num_cells);
    }
}

// round 15
// speedup vs baseline: 1.0192x; 1.0192x over previous
#include <cuda_runtime.h>
#include <cuda_fp16.h>
#include <cstdint>

// Problem shape (fixed by the dataset)
#define D_IN     256
#define D_OUT    512
#define MAX_M    50048            // multiple of 128 (and of 64)
#define MAX_CHUNKS 100096

// GEMM tiling: CTA 64(M) x 128(N), warp tile 32x32, 8 warps, 3 CTA/SM
#define TILE_M 64
#define TILE_N 128
#define BK     64                     // fp16 per K-chunk (128 bytes per row)
#define NCHUNKS (D_IN / BK)           // 4
#define A_BYTES (TILE_M * 128)        // 8KB
#define B_BYTES (TILE_N * 128)        // 16KB
#define STAGE_BYTES (A_BYTES + B_BYTES)   // 24KB
#define NSTAGES 3
#define SMEM_TOTAL (NSTAGES * STAGE_BYTES)   // 72KB

// ---------------------------------------------------------------------------
// Scratch (device globals — allocation-free rule)
// ---------------------------------------------------------------------------
__device__ __half g_feat16[(size_t)MAX_CHUNKS * D_IN];   // fp16 chunk table
__device__ __half g_a[(size_t)MAX_M * D_IN];             // cell means, fp16
__device__ __half g_b[(size_t)D_OUT * D_IN];             // W^T [512][256] fp16
__device__ int g_starts[MAX_M + 2];

// ---------------------------------------------------------------------------
// PTX helpers (legacy tensor-core path — tcgen05 NOT available through the
// harness's compute_103 virtual target)
// ---------------------------------------------------------------------------
__device__ __forceinline__ uint32_t smem_u32(const void* p) {
    uint32_t a;
    asm("{ .reg .u64 t; cvta.to.shared.u64 t, %1; cvt.u32.u64 %0, t; }"
        : "=r"(a) : "l"(p));
    return a;
}

#define CP_ASYNC16(dst_u32, src_ptr) \
    asm volatile("cp.async.cg.shared.global [%0], [%1], 16;" \
                 :: "r"(dst_u32), "l"(src_ptr))
#define CP_COMMIT() asm volatile("cp.async.commit_group;" ::: "memory")
#define CP_WAIT(n)  asm volatile("cp.async.wait_group %0;" :: "n"(n) : "memory")

#define LDSM_X4(r0, r1, r2, r3, addr) \
    asm volatile("ldmatrix.sync.aligned.m8n8.x4.shared.b16 {%0,%1,%2,%3}, [%4];" \
                 : "=r"(r0), "=r"(r1), "=r"(r2), "=r"(r3) : "r"(addr))

#define MMA_F16(d, a, b) \
    asm volatile( \
        "mma.sync.aligned.m16n8k16.row.col.f32.f16.f16.f32 " \
        "{%0,%1,%2,%3}, {%4,%5,%6,%7}, {%8,%9}, {%0,%1,%2,%3};" \
        : "+f"((d)[0]), "+f"((d)[1]), "+f"((d)[2]), "+f"((d)[3]) \
        : "r"((a)[0]), "r"((a)[1]), "r"((a)[2]), "r"((a)[3]), \
          "r"((b)[0]), "r"((b)[1]))

// SW128-style swizzle for 128B rows
__device__ __forceinline__ uint32_t sw_off(int row, int colbyte) {
    return (uint32_t)(row * 128 + (colbyte ^ ((row & 7) << 4)));
}

__device__ __forceinline__ uint32_t pack_h2(float x, float y) {
    __half2 h = __floats2half2_rn(x, y);
    return *reinterpret_cast<uint32_t*>(&h);
}

// ---------------------------------------------------------------------------
// Prep kernel: block-range dispatch.
//   [0, FB)            : chunk_features fp32 -> fp16 (16 floats / thread)
//   [FB, FB+512)       : W transpose + fp16 convert
//   [FB+512, ...)      : per-cell start offsets (scatter from boundaries)
// ---------------------------------------------------------------------------
__global__ void prep_kernel(const float* __restrict__ feats,
                            const float* __restrict__ W,
                            const int* __restrict__ seg,
                            int n_feat_elems, int FB,
                            int M, int num_cells) {
    int b = blockIdx.x;
    if (b < FB) {
        int base = (b * 256 + threadIdx.x) * 16;
        if (base + 16 <= n_feat_elems) {
            float4 v0 = __ldg(reinterpret_cast<const float4*>(feats + base));
            float4 v1 = __ldg(reinterpret_cast<const float4*>(feats + base + 4));
            float4 v2 = __ldg(reinterpret_cast<const float4*>(feats + base + 8));
            float4 v3 = __ldg(reinterpret_cast<const float4*>(feats + base + 12));
            uint4 p0, p1;
            p0.x = pack_h2(v0.x, v0.y); p0.y = pack_h2(v0.z, v0.w);
            p0.z = pack_h2(v1.x, v1.y); p0.w = pack_h2(v1.z, v1.w);
            p1.x = pack_h2(v2.x, v2.y); p1.y = pack_h2(v2.z, v2.w);
            p1.z = pack_h2(v3.x, v3.y); p1.w = pack_h2(v3.z, v3.w);
            *reinterpret_cast<uint4*>(g_feat16 + base)     = p0;
            *reinterpret_cast<uint4*>(g_feat16 + base + 8) = p1;
        }
    } else if (b < FB + 512) {
        int idx = (b - FB) * 256 + threadIdx.x;   // 0..131071
        int k = idx >> 9;                         // / 512
        int n = idx & 511;
        g_b[(size_t)n * D_IN + k] = __float2half(W[idx]);
    } else {
        int i = (b - FB - 512) * 256 + threadIdx.x;
        if (i >= M) return;
        int cur = seg[i];
        int prev = (i == 0) ? -1 : seg[i - 1];
        for (int c = prev + 1; c <= cur; ++c) g_starts[c] = i;
        if (i == M - 1)
            for (int c = cur + 1; c <= num_cells; ++c) g_starts[c] = M;
    }
}

// ---------------------------------------------------------------------------
// seg_mean: warp-per-cell gather (fp16 rows) + fp32 mean -> fp16 A
// 4-way unrolled member loop (MLP=4 independent row loads in flight).
// ---------------------------------------------------------------------------
__device__ __forceinline__ void acc_row(float* acc, uint4 v) {
    float2 f0 = __half22float2(*reinterpret_cast<__half2*>(&v.x));
    float2 f1 = __half22float2(*reinterpret_cast<__half2*>(&v.y));
    float2 f2 = __half22float2(*reinterpret_cast<__half2*>(&v.z));
    float2 f3 = __half22float2(*reinterpret_cast<__half2*>(&v.w));
    acc[0] += f0.x; acc[1] += f0.y; acc[2] += f1.x; acc[3] += f1.y;
    acc[4] += f2.x; acc[5] += f2.y; acc[6] += f3.x; acc[7] += f3.y;
}

__global__ void seg_mean_kernel(const int* __restrict__ midx, int num_cells) {
    int warp = (blockIdx.x * blockDim.x + threadIdx.x) >> 5;
    int lane = threadIdx.x & 31;
    if (warp >= num_cells) return;

    int s = g_starts[warp];
    int e = g_starts[warp + 1];

    float acc[8];
    #pragma unroll
    for (int i = 0; i < 8; ++i) acc[i] = 0.f;

    int j = s;
    for (; j + 4 <= e; j += 4) {
        int i0 = __ldg(midx + j);
        int i1 = __ldg(midx + j + 1);
        int i2 = __ldg(midx + j + 2);
        int i3 = __ldg(midx + j + 3);
        uint4 v0 = __ldg(reinterpret_cast<const uint4*>(
                             g_feat16 + (size_t)i0 * D_IN) + lane);
        uint4 v1 = __ldg(reinterpret_cast<const uint4*>(
                             g_feat16 + (size_t)i1 * D_IN) + lane);
        uint4 v2 = __ldg(reinterpret_cast<const uint4*>(
                             g_feat16 + (size_t)i2 * D_IN) + lane);
        uint4 v3 = __ldg(reinterpret_cast<const uint4*>(
                             g_feat16 + (size_t)i3 * D_IN) + lane);
        acc_row(acc, v0);
        acc_row(acc, v1);
        acc_row(acc, v2);
        acc_row(acc, v3);
    }
    for (; j < e; ++j) {
        uint4 v = __ldg(reinterpret_cast<const uint4*>(
                            g_feat16 + (size_t)__ldg(midx + j) * D_IN) + lane);
        acc_row(acc, v);
    }

    int cnt = e - s;
    float inv = 1.0f / (float)(cnt > 0 ? cnt : 1);

    uint4 p;
    p.x = pack_h2(acc[0] * inv, acc[1] * inv);
    p.y = pack_h2(acc[2] * inv, acc[3] * inv);
    p.z = pack_h2(acc[4] * inv, acc[5] * inv);
    p.w = pack_h2(acc[6] * inv, acc[7] * inv);
    *reinterpret_cast<uint4*>(g_a + (size_t)warp * D_IN + 8 * lane) = p;
}

// ---------------------------------------------------------------------------
// GEMM: mma.sync fp16  out[M,512] = A[M,256] @ W[256,512] + bias
// CTA tile 64(M) x 128(N); warp tile 32x32 (wm in 0..1, wn in 0..3).
// 3-stage cp.async pipeline (24KB/stage), proven R9 sync ordering.
// Low regs (~75) + 72KB smem -> 3 CTAs/SM = 24 warps for latency hiding.
// ---------------------------------------------------------------------------
__device__ __forceinline__ void load_stage(uint32_t stage_u32, int m_base,
                                           int n_base, int kchunk) {
    int tid = threadIdx.x;
    const char* gA = reinterpret_cast<const char*>(g_a);
    const char* gB = reinterpret_cast<const char*>(g_b);
    int kbyte = kchunk * BK * 2;
    // A: 8KB = 512 x 16B segments (2 per thread)
    #pragma unroll
    for (int i = 0; i < 2; ++i) {
        int seg = tid + i * 256;           // 0..511
        int r = seg >> 3;                  // 0..63
        int cb = (seg & 7) << 4;           // 0..112
        CP_ASYNC16(stage_u32 + sw_off(r, cb),
                   gA + (size_t)(m_base + r) * (D_IN * 2) + kbyte + cb);
    }
    // B: 16KB = 1024 x 16B segments (4 per thread)
    #pragma unroll
    for (int i = 0; i < 4; ++i) {
        int seg = tid + i * 256;           // 0..1023
        int r = seg >> 3;                  // 0..127
        int cb = (seg & 7) << 4;           // 0..112
        CP_ASYNC16(stage_u32 + A_BYTES + sw_off(r, cb),
                   gB + (size_t)(n_base + r) * (D_IN * 2) + kbyte + cb);
    }
}

__global__ __launch_bounds__(256, 3)
void gemm_kernel(const float* __restrict__ bias, float* __restrict__ out, int M) {
    extern __shared__ char smem[];
    uint32_t sb = smem_u32(smem);

    int tid  = threadIdx.x;
    int wid  = tid >> 5;
    int lane = tid & 31;
    int wm = wid >> 2;           // 0..1  (M direction, 32 rows each)
    int wn = wid & 3;            // 0..3  (N direction, 32 cols each)

    int m_base = blockIdx.y * TILE_M;
    int n_base = blockIdx.x * TILE_N;

    float acc[2][4][4];
    #pragma unroll
    for (int mt = 0; mt < 2; ++mt)
        #pragma unroll
        for (int nt = 0; nt < 4; ++nt)
            #pragma unroll
            for (int j = 0; j < 4; ++j)
                acc[mt][nt][j] = 0.f;

    // Prologue: fill first 2 of 3 stages
    load_stage(sb, m_base, n_base, 0);
    CP_COMMIT();
    load_stage(sb + STAGE_BYTES, m_base, n_base, 1);
    CP_COMMIT();

    // ldmatrix lane offsets
    int a_row  = wm * 32 + (lane & 15);                     // + mt*16
    int a_cgrp = (lane >> 4) << 4;                          // 0 or 16
    int b_m    = lane >> 3;                                 // matrix idx 0..3
    int b_row  = wn * 32 + ((b_m >> 1) << 3) + (lane & 7);  // + ntp*16
    int b_cgrp = (b_m & 1) << 4;                            // 0 or 16

    #pragma unroll
    for (int c = 0; c < NCHUNKS; ++c) {
        CP_WAIT(1);          // chunk c resident (this thread's copies)
        __syncthreads();     // cross-thread visibility of cp.async data

        if (c + 2 < NCHUNKS)
            load_stage(sb + (uint32_t)((c + 2) % NSTAGES) * STAGE_BYTES,
                       m_base, n_base, c + 2);
        CP_COMMIT();         // may be empty; keeps group accounting in lockstep

        uint32_t stage = sb + (uint32_t)(c % NSTAGES) * STAGE_BYTES;

        #pragma unroll
        for (int ks = 0; ks < 4; ++ks) {
            int kb = ks * 32;
            uint32_t a[2][4];
            #pragma unroll
            for (int mt = 0; mt < 2; ++mt) {
                uint32_t off = sw_off(a_row + mt * 16, kb + a_cgrp);
                LDSM_X4(a[mt][0], a[mt][1], a[mt][2], a[mt][3], stage + off);
            }
            uint32_t b[4][2];
            #pragma unroll
            for (int ntp = 0; ntp < 2; ++ntp) {
                uint32_t off = sw_off(b_row + ntp * 16, kb + b_cgrp);
                LDSM_X4(b[2*ntp][0], b[2*ntp][1], b[2*ntp+1][0], b[2*ntp+1][1],
                        stage + A_BYTES + off);
            }
            #pragma unroll
            for (int mt = 0; mt < 2; ++mt)
                #pragma unroll
                for (int nt = 0; nt < 4; ++nt)
                    MMA_F16(acc[mt][nt], a[mt], b[nt]);
        }
    }

    // Epilogue: bias add + guarded stores
    int g = lane >> 2;           // row within m16 tile
    int q = lane & 3;            // col pair within n8 tile
    #pragma unroll
    for (int mt = 0; mt < 2; ++mt) {
        int r0 = m_base + wm * 32 + mt * 16 + g;
        #pragma unroll
        for (int nt = 0; nt < 4; ++nt) {
            int col = n_base + wn * 32 + nt * 8 + q * 2;
            float2 bv = *reinterpret_cast<const float2*>(bias + col);
            if (r0 < M) {
                float2 o = make_float2(acc[mt][nt][0] + bv.x,
                                       acc[mt][nt][1] + bv.y);
                *reinterpret_cast<float2*>(out + (size_t)r0 * D_OUT + col) = o;
            }
            if (r0 + 8 < M) {
                float2 o = make_float2(acc[mt][nt][2] + bv.x,
                                       acc[mt][nt][3] + bv.y);
                *reinterpret_cast<float2*>(out + (size_t)(r0 + 8) * D_OUT + col) = o;
            }
        }
    }
}

// ---------------------------------------------------------------------------
// Launch
// Inputs (metadata order): chunk_features, member_idx, segment_ids, num_cells, W, b
// ---------------------------------------------------------------------------
extern "C" void kernel_launch(void* const* d_in, const int* in_sizes, int n_in,
                              void* d_out, int out_size) {
    const float* feats = (const float*)d_in[0];
    const int*   midx  = (const int*)d_in[1];
    const int*   seg   = (const int*)d_in[2];
    const float* W     = (const float*)d_in[4];
    const float* bias  = (const float*)d_in[5];
    float* out = (float*)d_out;

    int n_feat    = in_sizes[0];          // 25.6M floats
    int M_members = in_sizes[1];          // 400000
    int num_cells = out_size / D_OUT;     // 50000

    // A: fused prep — feats fp16 convert | W transpose+convert | seg starts
    {
        int FB = (n_feat / 16 + 255) / 256;                 // feats blocks
        int SB = (M_members + 255) / 256;                   // starts blocks
        prep_kernel<<<FB + 512 + SB, 256>>>(feats, W, seg,
                                            n_feat, FB, M_members, num_cells);
    }

    // B: gather + segment mean (fp16 table) -> fp16 A
    {
        int total_threads = num_cells * 32;
        seg_mean_kernel<<<(total_threads + 255) / 256, 256>>>(midx, num_cells);
    }

    // C: tensor-core projection GEMM + bias (64x128 tiles, 3 CTA/SM)
    {
        static bool attr_set = false;
        if (!attr_set) {
            cudaFuncSetAttribute(gemm_kernel,
                                 cudaFuncAttributeMaxDynamicSharedMemorySize,
                                 SMEM_TOTAL);
            attr_set = true;
        }
        dim3 grid(D_OUT / TILE_N, (num_cells + TILE_M - 1) / TILE_M);
        gemm_kernel<<<grid, 256, SMEM_TOTAL>>>(bias, out, num_cells);
    }
}